// round 8
// baseline (speedup 1.0000x reference)
#include <cuda_runtime.h>
#include <cuda_bf16.h>

// Shapes (fixed)
#define BB   8
#define NN   16384
#define SS   1024
#define TT   2
#define TPB  128
#define NPT  8

// Scratch: per-(batch,s) min-over-n as order-preserving uint keys.
__device__ unsigned int g_smin[24576];
// [0]=n-side sum chamfer1, [1]=chamfer2, [2]=consistency sq-sum
__device__ double g_acc[4];

__device__ __forceinline__ unsigned int f2key(float f) {
    unsigned int u = __float_as_uint(f);
    return u ^ ((unsigned int)((int)u >> 31) | 0x80000000u);
}
__device__ __forceinline__ float key2f(unsigned int k) {
    unsigned int u = (k & 0x80000000u) ? (k ^ 0x80000000u) : ~k;
    return __uint_as_float(u);
}

__device__ __forceinline__ unsigned long long bcast2(float f) {
    unsigned long long r;
    asm("mov.b64 %0, {%1, %1};" : "=l"(r) : "f"(f));
    return r;
}
__device__ __forceinline__ unsigned long long pack2(float lo, float hi) {
    unsigned long long r;
    asm("mov.b64 %0, {%1, %2};" : "=l"(r) : "f"(lo), "f"(hi));
    return r;
}
__device__ __forceinline__ unsigned long long ffma2(unsigned long long a,
                                                    unsigned long long b,
                                                    unsigned long long c) {
    unsigned long long d;
    asm("fma.rn.f32x2 %0, %1, %2, %3;" : "=l"(d) : "l"(a), "l"(b), "l"(c));
    return d;
}

__device__ __forceinline__ float block_reduce_sum(float v, float* sh) {
    #pragma unroll
    for (int o = 16; o > 0; o >>= 1) v += __shfl_down_sync(0xffffffffu, v, o);
    int lane = threadIdx.x & 31, w = threadIdx.x >> 5;
    if (lane == 0) sh[w] = v;
    __syncthreads();
    float r = 0.f;
    if (w == 0) {
        r = (lane < (int)(blockDim.x >> 5)) ? sh[lane] : 0.f;
        #pragma unroll
        for (int o = 16; o > 0; o >>= 1) r += __shfl_down_sync(0xffffffffu, r, o);
    }
    return r; // thread 0
}

__global__ void k_reset() {
    int i = blockIdx.x * blockDim.x + threadIdx.x;   // 24 x 256 = 6144 uint4
    ((uint4*)g_smin)[i] = make_uint4(0xffffffffu, 0xffffffffu, 0xffffffffu, 0xffffffffu);
    if (i < 4) g_acc[i] = 0.0;
}

// Fused kernel: 896 blocks x 128 threads.
//  [0,128)   A: n-side chamfer1  (gt vs sp)          -> g_acc[0]
//  [128,384) B: n-side chamfer2  (tgt vs tsp)        -> g_acc[1]
//  [384,512) C: s-side chamfer1  (sp vs gt chunk)    -> g_smin[0..8192)
//  [512,768) D: s-side chamfer2  (tsp vs tgt chunk)  -> g_smin[8192..)
//  [768,896) E: consistency MSE                      -> g_acc[2]
__global__ void __launch_bounds__(TPB) k_fused(
        const float* __restrict__ gt, const float* __restrict__ sp,
        const float* __restrict__ tgt, const float* __restrict__ tsp,
        const float* __restrict__ tm) {
    __shared__ __align__(16) unsigned long long ytile[4096]; // 1024 pts x 32B
    __shared__ float red[32];
    int blk = blockIdx.x;
    int tid = threadIdx.x;

    if (blk >= 768) {
        // ---- consistency term ----
        int i = (blk - 768) * TPB + tid;      // 0..16383
        int t = i >> 13;
        int rem = i & 8191;
        const float* p = sp + 3 * rem;
        float a = p[0], b = p[1], c = p[2];
        const float* M = tm + 9 * t;
        float acc = 0.f;
        #pragma unroll
        for (int e = 0; e < 3; e++) {
            float v = fmaf(a, M[e], fmaf(b, M[3 + e], c * M[6 + e]));
            float diff = v - tsp[(size_t)i * 3 + e];
            acc = fmaf(diff, diff, acc);
        }
        float bsum = block_reduce_sum(acc, red);
        if (tid == 0) atomicAdd(&g_acc[2], (double)bsum);
        return;
    }

    const float* smem_src;   // 1024 pts -> smem as broadcast-packed (-2p, |p|^2)
    const float* thr_src;    // 1024 pts held in registers (8 per thread)
    bool nside;
    int target;

    if (blk < 128) {                       // A
        int b = blk >> 4, chunk = blk & 15;
        smem_src = sp + (size_t)b * SS * 3;
        thr_src  = gt + (size_t)b * NN * 3 + (size_t)chunk * 1024 * 3;
        nside = true; target = 0;
    } else if (blk < 384) {                // B
        int idx = blk - 128, tb = idx >> 4, chunk = idx & 15;
        smem_src = tsp + (size_t)tb * SS * 3;
        thr_src  = tgt + (size_t)tb * NN * 3 + (size_t)chunk * 1024 * 3;
        nside = true; target = 1;
    } else if (blk < 512) {                // C
        int idx = blk - 384, b = idx >> 4, chunk = idx & 15;
        smem_src = gt + (size_t)b * NN * 3 + (size_t)chunk * 1024 * 3;
        thr_src  = sp + (size_t)b * SS * 3;
        nside = false; target = b * SS;
    } else {                               // D
        int idx = blk - 512, tb = idx >> 4, chunk = idx & 15;
        smem_src = tgt + (size_t)tb * NN * 3 + (size_t)chunk * 1024 * 3;
        thr_src  = tsp + (size_t)tb * SS * 3;
        nside = false; target = 8192 + tb * SS;
    }

    // Fill broadcast-packed tile: (-2x,-2x)(-2y,-2y)(-2z,-2z)(sq,sq)
    for (int i = tid; i < 1024; i += TPB) {
        const float* p = smem_src + 3 * i;
        float a = p[0], b = p[1], c = p[2];
        float sqv = fmaf(a, a, fmaf(b, b, c * c));
        ytile[4 * i + 0] = bcast2(-2.f * a);
        ytile[4 * i + 1] = bcast2(-2.f * b);
        ytile[4 * i + 2] = bcast2(-2.f * c);
        ytile[4 * i + 3] = bcast2(sqv);
    }
    __syncthreads();

    // 8 thread-private points, packed as 4 f32x2 triples
    float a0[NPT], a1[NPT], a2[NPT], sqx[NPT], mn[NPT];
    #pragma unroll
    for (int k = 0; k < NPT; k++) {
        const float* p = thr_src + 3 * (tid + k * TPB);
        a0[k] = p[0]; a1[k] = p[1]; a2[k] = p[2];
        sqx[k] = fmaf(a0[k], a0[k], fmaf(a1[k], a1[k], a2[k] * a2[k]));
        mn[k] = 3.4e38f;
    }
    unsigned long long x0p[4], x1p[4], x2p[4];
    #pragma unroll
    for (int kk = 0; kk < 4; kk++) {
        x0p[kk] = pack2(a0[2*kk], a0[2*kk+1]);
        x1p[kk] = pack2(a1[2*kk], a1[2*kk+1]);
        x2p[kk] = pack2(a2[2*kk], a2[2*kk+1]);
    }

    // Core loop: 12 FFMA2 per thread-step covers 8 pairs (1.5 fma-slots/pair)
    const ulonglong2* yt = (const ulonglong2*)ytile;
    #pragma unroll 2
    for (int s = 0; s < 1024; s++) {
        ulonglong2 ya = yt[2 * s];       // (-2x|-2x), (-2y|-2y)
        ulonglong2 yb = yt[2 * s + 1];   // (-2z|-2z), (sq|sq)
        #pragma unroll
        for (int kk = 0; kk < 4; kk++) {
            unsigned long long v = ffma2(ya.x, x0p[kk], yb.y);
            v = ffma2(ya.y, x1p[kk], v);
            v = ffma2(yb.x, x2p[kk], v);
            float lo, hi;
            asm("mov.b64 {%0, %1}, %2;" : "=f"(lo), "=f"(hi) : "l"(v));
            mn[2*kk]   = fminf(mn[2*kk],   lo);
            mn[2*kk+1] = fminf(mn[2*kk+1], hi);
        }
    }

    if (nside) {
        float s8 = 0.f;
        #pragma unroll
        for (int k = 0; k < NPT; k++) s8 += mn[k] + sqx[k];
        float bs = block_reduce_sum(s8, red);
        if (tid == 0) atomicAdd(&g_acc[target], (double)bs);
    } else {
        #pragma unroll
        for (int k = 0; k < NPT; k++)
            atomicMin(&g_smin[target + tid + k * TPB], f2key(mn[k] + sqx[k]));
    }
}

__global__ void k_final(float* __restrict__ out) {
    __shared__ double sh1[32], sh2[32];
    double s1 = 0.0, s2 = 0.0;
    for (int i = threadIdx.x; i < 8192; i += blockDim.x)
        s1 += (double)key2f(g_smin[i]);
    for (int i = 8192 + threadIdx.x; i < 24576; i += blockDim.x)
        s2 += (double)key2f(g_smin[i]);
    #pragma unroll
    for (int o = 16; o > 0; o >>= 1) {
        s1 += __shfl_down_sync(0xffffffffu, s1, o);
        s2 += __shfl_down_sync(0xffffffffu, s2, o);
    }
    int lane = threadIdx.x & 31, w = threadIdx.x >> 5;
    if (lane == 0) { sh1[w] = s1; sh2[w] = s2; }
    __syncthreads();
    if (threadIdx.x == 0) {
        int nw = blockDim.x >> 5;
        double t1 = 0.0, t2 = 0.0;
        for (int j = 0; j < nw; j++) { t1 += sh1[j]; t2 += sh2[j]; }
        double mean_s1 = t1 / (double)(BB * SS);
        double mean_n1 = g_acc[0] / (double)(BB * NN);
        double c1 = 0.5 * (mean_s1 + mean_n1);
        double mean_s2 = t2 / (double)(TT * BB * SS);
        double mean_n2 = g_acc[1] / (double)(TT * BB * NN);
        double c2 = 0.5 * (mean_s2 + mean_n2);
        double cd = (c1 + c2) / (double)(TT + 1);
        double mse = g_acc[2] / (double)(TT * BB * SS * 3) * 1000.0;
        out[0] = (float)(cd + mse);
    }
}

extern "C" void kernel_launch(void* const* d_in, const int* in_sizes, int n_in,
                              void* d_out, int out_size) {
    const float* gt  = (const float*)d_in[0];  // [B,N,3]
    const float* sp  = (const float*)d_in[1];  // [B,S,3]
    const float* tgt = (const float*)d_in[2];  // [T,B,N,3]
    const float* tsp = (const float*)d_in[3];  // [T,B,S,3]
    const float* tm  = (const float*)d_in[4];  // [T,3,3]
    float* out = (float*)d_out;

    k_reset<<<24, 256>>>();
    k_fused<<<896, TPB>>>(gt, sp, tgt, tsp, tm);
    k_final<<<1, 1024>>>(out);
}

// round 9
// speedup vs baseline: 1.0279x; 1.0279x over previous
#include <cuda_runtime.h>
#include <cuda_bf16.h>

// Shapes (fixed)
#define BB   8
#define NN   16384
#define SS   1024
#define TT   2
#define TPB  128
#define NPT  8

// Per-block result slots — every slot written on every call, no reset needed.
__device__ float  g_nsum[384];            // roles A,B: per-block n-side sums
__device__ float  g_pmin[16 * 24576];     // roles C,D: per-chunk partial mins
__device__ float  g_csum[128];            // role E: consistency block sums
__device__ double g_f1[48], g_f2[48];     // final1 partials (chamfer1/2 s-side)

__device__ __forceinline__ float block_reduce_sum(float v, float* sh) {
    #pragma unroll
    for (int o = 16; o > 0; o >>= 1) v += __shfl_down_sync(0xffffffffu, v, o);
    int lane = threadIdx.x & 31, w = threadIdx.x >> 5;
    if (lane == 0) sh[w] = v;
    __syncthreads();
    float r = 0.f;
    if (w == 0) {
        r = (lane < (int)(blockDim.x >> 5)) ? sh[lane] : 0.f;
        #pragma unroll
        for (int o = 16; o > 0; o >>= 1) r += __shfl_down_sync(0xffffffffu, r, o);
    }
    return r; // thread 0
}

// Fused kernel: 896 blocks x 128 threads. Every chamfer block: 1024x1024 pairs.
//  [0,128)   A: n-side chamfer1  (gt vs sp)          -> g_nsum[blk]
//  [128,384) B: n-side chamfer2  (tgt vs tsp)        -> g_nsum[blk]
//  [384,512) C: s-side chamfer1  partial mins        -> g_pmin[chunk][b*SS+s]
//  [512,768) D: s-side chamfer2  partial mins        -> g_pmin[chunk][8192+tb*SS+s]
//  [768,896) E: consistency MSE                      -> g_csum[blk-768]
__global__ void __launch_bounds__(TPB) k_fused(
        const float* __restrict__ gt, const float* __restrict__ sp,
        const float* __restrict__ tgt, const float* __restrict__ tsp,
        const float* __restrict__ tm) {
    __shared__ float4 ypts[1024];   // (-2x,-2y,-2z,|p|^2)
    __shared__ float red[32];
    int blk = blockIdx.x;
    int tid = threadIdx.x;

    if (blk >= 768) {
        // ---- consistency term ----
        int i = (blk - 768) * TPB + tid;      // 0..16383
        int t = i >> 13;
        int rem = i & 8191;
        const float* p = sp + 3 * rem;
        float a = p[0], b = p[1], c = p[2];
        const float* M = tm + 9 * t;
        float acc = 0.f;
        #pragma unroll
        for (int e = 0; e < 3; e++) {
            float v = fmaf(a, M[e], fmaf(b, M[3 + e], c * M[6 + e]));
            float diff = v - tsp[(size_t)i * 3 + e];
            acc = fmaf(diff, diff, acc);
        }
        float bsum = block_reduce_sum(acc, red);
        if (tid == 0) g_csum[blk - 768] = bsum;
        return;
    }

    const float* smem_src;   // 1024 pts -> smem tile
    const float* thr_src;    // 1024 pts -> registers (8 per thread)
    bool nside;
    int target;              // g_pmin row base for s-side

    if (blk < 128) {                       // A
        int b = blk >> 4, chunk = blk & 15;
        smem_src = sp + (size_t)b * SS * 3;
        thr_src  = gt + (size_t)b * NN * 3 + (size_t)chunk * 1024 * 3;
        nside = true; target = 0;
    } else if (blk < 384) {                // B
        int idx = blk - 128, tb = idx >> 4, chunk = idx & 15;
        smem_src = tsp + (size_t)tb * SS * 3;
        thr_src  = tgt + (size_t)tb * NN * 3 + (size_t)chunk * 1024 * 3;
        nside = true; target = 0;
    } else if (blk < 512) {                // C
        int idx = blk - 384, b = idx >> 4, chunk = idx & 15;
        smem_src = gt + (size_t)b * NN * 3 + (size_t)chunk * 1024 * 3;
        thr_src  = sp + (size_t)b * SS * 3;
        nside = false; target = chunk * 24576 + b * SS;
    } else {                               // D
        int idx = blk - 512, tb = idx >> 4, chunk = idx & 15;
        smem_src = tgt + (size_t)tb * NN * 3 + (size_t)chunk * 1024 * 3;
        thr_src  = tsp + (size_t)tb * SS * 3;
        nside = false; target = chunk * 24576 + 8192 + tb * SS;
    }

    // Shared tile: (-2x, -2y, -2z, x^2+y^2+z^2)
    for (int i = tid; i < 1024; i += TPB) {
        const float* p = smem_src + 3 * i;
        float a = p[0], b = p[1], c = p[2];
        float sqv = fmaf(a, a, fmaf(b, b, c * c));
        ypts[i] = make_float4(-2.f * a, -2.f * b, -2.f * c, sqv);
    }
    __syncthreads();

    // 8 thread-private points
    float x0[NPT], x1[NPT], x2[NPT], sqx[NPT], mn[NPT];
    #pragma unroll
    for (int k = 0; k < NPT; k++) {
        const float* p = thr_src + 3 * (tid + k * TPB);
        x0[k] = p[0]; x1[k] = p[1]; x2[k] = p[2];
        sqx[k] = fmaf(x0[k], x0[k], fmaf(x1[k], x1[k], x2[k] * x2[k]));
        mn[k] = 3.4e38f;
    }

    // Core loop: per s = 1 LDS.128 + 24 FFMA + 8 FMNMX for 8 pairs
    #pragma unroll 2
    for (int s = 0; s < 1024; s++) {
        float4 y = ypts[s];
        #pragma unroll
        for (int k = 0; k < NPT; k++) {
            float v = fmaf(y.x, x0[k], y.w);
            v = fmaf(y.y, x1[k], v);
            v = fmaf(y.z, x2[k], v);
            mn[k] = fminf(mn[k], v);
        }
    }

    if (nside) {
        float s8 = 0.f;
        #pragma unroll
        for (int k = 0; k < NPT; k++) s8 += mn[k] + sqx[k];
        float bs = block_reduce_sum(s8, red);
        if (tid == 0) g_nsum[blk] = bs;
    } else {
        #pragma unroll
        for (int k = 0; k < NPT; k++)
            g_pmin[target + tid + k * TPB] = mn[k] + sqx[k];
    }
}

// Stage 1: min over 16 chunks per (b,s) row, partial sums per block.
// 48 blocks x 256 threads; block handles 512 rows (either all chamfer1 or all chamfer2).
__global__ void k_final1() {
    __shared__ float red[32];
    int row0 = blockIdx.x * 512;
    float s = 0.f;
    for (int r = row0 + threadIdx.x; r < row0 + 512; r += 256) {
        float m = g_pmin[r];
        #pragma unroll
        for (int c = 1; c < 16; c++) m = fminf(m, g_pmin[c * 24576 + r]);
        s += m;
    }
    float bs = block_reduce_sum(s, red);
    if (threadIdx.x == 0) {
        if (blockIdx.x < 16) { g_f1[blockIdx.x] = (double)bs; g_f2[blockIdx.x] = 0.0; }
        else                 { g_f1[blockIdx.x] = 0.0;        g_f2[blockIdx.x] = (double)bs; }
    }
}

// Stage 2: combine everything.
__global__ void k_final2(float* __restrict__ out) {
    __shared__ double sh[32 * 5];
    double v1 = 0, v2 = 0, n1 = 0, n2 = 0, cs = 0;
    int t = threadIdx.x;             // 512 threads
    if (t < 48) { v1 = g_f1[t]; v2 = g_f2[t]; }
    if (t < 128) n1 = (double)g_nsum[t];
    if (t < 256) n2 = (double)g_nsum[128 + t] + ((t < 128) ? (double)g_nsum[256 + t] : 0.0);
    if (t < 128) cs = (double)g_csum[t];
    #pragma unroll
    for (int o = 16; o > 0; o >>= 1) {
        v1 += __shfl_down_sync(0xffffffffu, v1, o);
        v2 += __shfl_down_sync(0xffffffffu, v2, o);
        n1 += __shfl_down_sync(0xffffffffu, n1, o);
        n2 += __shfl_down_sync(0xffffffffu, n2, o);
        cs += __shfl_down_sync(0xffffffffu, cs, o);
    }
    int lane = t & 31, w = t >> 5;   // 16 warps
    if (lane == 0) {
        sh[w] = v1; sh[32 + w] = v2; sh[64 + w] = n1; sh[96 + w] = n2; sh[128 + w] = cs;
    }
    __syncthreads();
    if (t == 0) {
        double V1 = 0, V2 = 0, N1 = 0, N2 = 0, CS = 0;
        for (int j = 0; j < 16; j++) {
            V1 += sh[j]; V2 += sh[32 + j]; N1 += sh[64 + j]; N2 += sh[96 + j]; CS += sh[128 + j];
        }
        double mean_s1 = V1 / (double)(BB * SS);
        double mean_n1 = N1 / (double)(BB * NN);
        double c1 = 0.5 * (mean_s1 + mean_n1);
        double mean_s2 = V2 / (double)(TT * BB * SS);
        double mean_n2 = N2 / (double)(TT * BB * NN);
        double c2 = 0.5 * (mean_s2 + mean_n2);
        double cd = (c1 + c2) / (double)(TT + 1);
        double mse = CS / (double)(TT * BB * SS * 3) * 1000.0;
        out[0] = (float)(cd + mse);
    }
}

extern "C" void kernel_launch(void* const* d_in, const int* in_sizes, int n_in,
                              void* d_out, int out_size) {
    const float* gt  = (const float*)d_in[0];  // [B,N,3]
    const float* sp  = (const float*)d_in[1];  // [B,S,3]
    const float* tgt = (const float*)d_in[2];  // [T,B,N,3]
    const float* tsp = (const float*)d_in[3];  // [T,B,S,3]
    const float* tm  = (const float*)d_in[4];  // [T,3,3]
    float* out = (float*)d_out;

    k_fused<<<896, TPB>>>(gt, sp, tgt, tsp, tm);
    k_final1<<<48, 256>>>();
    k_final2<<<1, 512>>>(out);
}